// round 4
// baseline (speedup 1.0000x reference)
#include <cuda_runtime.h>
#include <math.h>

#define NB    4
#define NRES  56
#define NTOK  3136            // 56*56
#define DIMF  384
#define TDF   192
#define MTOT  12544           // NB*NTOK

typedef unsigned long long ull;

// packed f32x2 helpers (sm_100+ PTX; FFMA2 is PTX-only per SASS_QUICKREF)
__device__ __forceinline__ ull ffma2(ull a, ull b, ull c) {
    ull d; asm("fma.rn.f32x2 %0, %1, %2, %3;" : "=l"(d) : "l"(a), "l"(b), "l"(c)); return d;
}
__device__ __forceinline__ ull fmul2(ull a, ull b) {
    ull d; asm("mul.rn.f32x2 %0, %1, %2;" : "=l"(d) : "l"(a), "l"(b)); return d;
}
__device__ __forceinline__ ull pack2(float x, float y) {
    ull r; asm("mov.b64 %0, {%1, %2};" : "=l"(r) : "f"(x), "f"(y)); return r;
}
__device__ __forceinline__ float2 unpack2(ull v) {
    float2 r; asm("mov.b64 {%0, %1}, %2;" : "=f"(r.x), "=f"(r.y) : "l"(v)); return r;
}

// scratch (allocation-free rule: __device__ globals)
__device__ __align__(16) float g_tmp[(size_t)MTOT * DIMF];    // (m,384): 0..191 up, 192..383 dn
__device__ __align__(16) float g_qkv[(size_t)MTOT * 1152];    // (m,1152): 0..575 up qkv, 576..1151 dn qkv

// ---------------------------------------------------------------------------
// GEMM1: g_tmp[m,o] = sum_k xa[b,k,n] * W[o,k];  W = proj1 (o<192) / proj2
// ---------------------------------------------------------------------------
__global__ __launch_bounds__(256) void gemm1_kernel(
    const float* __restrict__ xa, const float* __restrict__ p1,
    const float* __restrict__ p2)
{
    __shared__ __align__(16) float As[16][260];
    __shared__ __align__(16) float Bs[16][68];
    int tid = threadIdx.x;
    int m0 = blockIdx.x * 256;
    int o0 = blockIdx.y * 64;
    const float* wb = (o0 < TDF) ? p1 : p2;
    int orow0 = (o0 < TDF) ? o0 : (o0 - TDF);

    int mm = m0 + tid;
    int bb = mm / NTOK;
    int nn = mm - bb * NTOK;
    const float* asrc = xa + (size_t)bb * DIMF * NTOK + nn;

    int b_ol = tid >> 2;
    int b_kq = tid & 3;

    ull acc2[8][4];
    #pragma unroll
    for (int i = 0; i < 8; i++)
        #pragma unroll
        for (int j = 0; j < 4; j++) acc2[i][j] = 0ull;

    int mr = (tid >> 4) * 16;
    int oc = (tid & 15) * 4;

    for (int k0 = 0; k0 < DIMF; k0 += 16) {
        #pragma unroll
        for (int k = 0; k < 16; k++)
            As[k][tid] = asrc[(size_t)(k0 + k) * NTOK];
        {
            float4 w4 = *(const float4*)(wb + (size_t)(orow0 + b_ol) * DIMF + k0 + b_kq * 4);
            Bs[b_kq*4+0][b_ol] = w4.x;
            Bs[b_kq*4+1][b_ol] = w4.y;
            Bs[b_kq*4+2][b_ol] = w4.z;
            Bs[b_kq*4+3][b_ol] = w4.w;
        }
        __syncthreads();
        #pragma unroll
        for (int k = 0; k < 16; k++) {
            const ulonglong2* ap = (const ulonglong2*)&As[k][mr];
            ull a2[8];
            #pragma unroll
            for (int q = 0; q < 4; q++) {
                ulonglong2 t = ap[q];
                a2[2*q] = t.x; a2[2*q+1] = t.y;
            }
            float4 bv = *(const float4*)&Bs[k][oc];
            ull b2[4];
            b2[0] = pack2(bv.x, bv.x); b2[1] = pack2(bv.y, bv.y);
            b2[2] = pack2(bv.z, bv.z); b2[3] = pack2(bv.w, bv.w);
            #pragma unroll
            for (int i = 0; i < 8; i++)
                #pragma unroll
                for (int j = 0; j < 4; j++)
                    acc2[i][j] = ffma2(a2[i], b2[j], acc2[i][j]);
        }
        __syncthreads();
    }
    #pragma unroll
    for (int i = 0; i < 8; i++) {
        float2 u0 = unpack2(acc2[i][0]);
        float2 u1 = unpack2(acc2[i][1]);
        float2 u2 = unpack2(acc2[i][2]);
        float2 u3 = unpack2(acc2[i][3]);
        *(float4*)(g_tmp + (size_t)(m0 + mr + 2*i)     * DIMF + o0 + oc) = make_float4(u0.x, u1.x, u2.x, u3.x);
        *(float4*)(g_tmp + (size_t)(m0 + mr + 2*i + 1) * DIMF + o0 + oc) = make_float4(u0.y, u1.y, u2.y, u3.y);
    }
}

// ---------------------------------------------------------------------------
// GEMM2: g_qkv[m,o] = sum_k g_tmp[m,koff+k] * W[o',k]  (K=192)
// ---------------------------------------------------------------------------
__global__ __launch_bounds__(256) void gemm2_kernel(
    const float* __restrict__ wu, const float* __restrict__ wd)
{
    __shared__ __align__(16) float As[16][260];
    __shared__ __align__(16) float Bs[16][68];
    int tid = threadIdx.x;
    int m0 = blockIdx.x * 256;
    int o0 = blockIdx.y * 64;
    const float* wb; int orow0, koff;
    if (o0 < 576) { wb = wu; orow0 = o0;       koff = 0;   }
    else          { wb = wd; orow0 = o0 - 576; koff = TDF; }

    int b_ol = tid >> 2;
    int b_kq = tid & 3;

    ull acc2[8][4];
    #pragma unroll
    for (int i = 0; i < 8; i++)
        #pragma unroll
        for (int j = 0; j < 4; j++) acc2[i][j] = 0ull;

    int mr = (tid >> 4) * 16;
    int oc = (tid & 15) * 4;
    const float* asrc = g_tmp + (size_t)(m0 + tid) * DIMF + koff;

    for (int k0 = 0; k0 < TDF; k0 += 16) {
        #pragma unroll
        for (int q = 0; q < 4; q++) {
            float4 a4 = *(const float4*)(asrc + k0 + q * 4);
            As[q*4+0][tid] = a4.x;
            As[q*4+1][tid] = a4.y;
            As[q*4+2][tid] = a4.z;
            As[q*4+3][tid] = a4.w;
        }
        {
            float4 w4 = *(const float4*)(wb + (size_t)(orow0 + b_ol) * TDF + k0 + b_kq * 4);
            Bs[b_kq*4+0][b_ol] = w4.x;
            Bs[b_kq*4+1][b_ol] = w4.y;
            Bs[b_kq*4+2][b_ol] = w4.z;
            Bs[b_kq*4+3][b_ol] = w4.w;
        }
        __syncthreads();
        #pragma unroll
        for (int k = 0; k < 16; k++) {
            const ulonglong2* ap = (const ulonglong2*)&As[k][mr];
            ull a2[8];
            #pragma unroll
            for (int q = 0; q < 4; q++) {
                ulonglong2 t = ap[q];
                a2[2*q] = t.x; a2[2*q+1] = t.y;
            }
            float4 bv = *(const float4*)&Bs[k][oc];
            ull b2[4];
            b2[0] = pack2(bv.x, bv.x); b2[1] = pack2(bv.y, bv.y);
            b2[2] = pack2(bv.z, bv.z); b2[3] = pack2(bv.w, bv.w);
            #pragma unroll
            for (int i = 0; i < 8; i++)
                #pragma unroll
                for (int j = 0; j < 4; j++)
                    acc2[i][j] = ffma2(a2[i], b2[j], acc2[i][j]);
        }
        __syncthreads();
    }
    #pragma unroll
    for (int i = 0; i < 8; i++) {
        float2 u0 = unpack2(acc2[i][0]);
        float2 u1 = unpack2(acc2[i][1]);
        float2 u2 = unpack2(acc2[i][2]);
        float2 u3 = unpack2(acc2[i][3]);
        *(float4*)(g_qkv + (size_t)(m0 + mr + 2*i)     * 1152 + o0 + oc) = make_float4(u0.x, u1.x, u2.x, u3.x);
        *(float4*)(g_qkv + (size_t)(m0 + mr + 2*i + 1) * 1152 + o0 + oc) = make_float4(u0.y, u1.y, u2.y, u3.y);
    }
}

// ---------------------------------------------------------------------------
// CSWin attention + fused LePE (unchanged from passing R3 kernel).
// ---------------------------------------------------------------------------
__global__ __launch_bounds__(416, 1) void cswin_kernel(
    const float* __restrict__ lw0, const float* __restrict__ lb0,
    const float* __restrict__ lw1, const float* __restrict__ lb1,
    float* __restrict__ out)
{
    extern __shared__ float smem[];
    float* sK = smem;                    // [392][48]
    float* sV = smem + 392 * 48;         // [392][48]
    float* sw = smem + 2 * 392 * 48;     // [9][48]
    float* sb = sw + 9 * 48;             // [48]

    int tid = threadIdx.x;
    int g  = blockIdx.x;
    int hd = blockIdx.y;
    int br = blockIdx.z;
    int wi = g & 7, b = g >> 3;
    int colq = br * 96 + hd * 48;

    {
        const float* lw = br ? lw1 : lw0;
        const float* lb = br ? lb1 : lb0;
        for (int idx = tid; idx < 432; idx += 416) {
            int nb = idx / 48, c = idx - nb * 48;
            sw[idx] = lw[(hd * 48 + c) * 9 + nb];
        }
        if (tid < 48) sb[tid] = lb[hd * 48 + tid];
    }
    for (int idx = tid; idx < 392 * 12; idx += 416) {
        int j = idx / 12, c4 = idx - j * 12;
        int node = (br == 0) ? ((j / 7) * NRES + wi * 7 + (j % 7)) : (wi * 392 + j);
        const float* base = g_qkv + (size_t)(b * NTOK + node) * 1152 + colq;
        ((float4*)(sK + j * 48))[c4] = ((const float4*)(base + TDF))[c4];
        ((float4*)(sV + j * 48))[c4] = ((const float4*)(base + 2 * TDF))[c4];
    }
    __syncthreads();
    if (tid >= 392) return;

    int t = tid;
    int node = (br == 0) ? ((t / 7) * NRES + wi * 7 + (t % 7)) : (wi * 392 + t);

    const float scale = 0.14433756729740643f;   // 1/sqrt(48)
    ull s2 = pack2(scale, scale);
    ull q2[24];
    {
        const ulonglong2* qp = (const ulonglong2*)(g_qkv + (size_t)(b * NTOK + node) * 1152 + colq);
        #pragma unroll
        for (int i = 0; i < 12; i++) {
            ulonglong2 v = qp[i];
            q2[2*i]   = fmul2(v.x, s2);
            q2[2*i+1] = fmul2(v.y, s2);
        }
    }
    ull O2[24];
    #pragma unroll
    for (int i = 0; i < 24; i++) O2[i] = 0ull;
    float mval = -1e30f, l = 0.f;

    for (int j0 = 0; j0 < 392; j0 += 8) {
        float s[8];
        #pragma unroll
        for (int jj = 0; jj < 8; jj++) {
            const ulonglong2* kr = (const ulonglong2*)(sK + (j0 + jj) * 48);
            ull acc = 0ull;
            #pragma unroll
            for (int i = 0; i < 12; i++) {
                ulonglong2 kv = kr[i];
                acc = ffma2(q2[2*i],   kv.x, acc);
                acc = ffma2(q2[2*i+1], kv.y, acc);
            }
            float2 u = unpack2(acc);
            s[jj] = u.x + u.y;
        }
        float cm = s[0];
        #pragma unroll
        for (int jj = 1; jj < 8; jj++) cm = fmaxf(cm, s[jj]);
        if (cm > mval) {
            float corr = __expf(mval - cm);
            ull c2 = pack2(corr, corr);
            l *= corr;
            #pragma unroll
            for (int i = 0; i < 24; i++) O2[i] = fmul2(O2[i], c2);
            mval = cm;
        }
        #pragma unroll
        for (int jj = 0; jj < 8; jj++) {
            float p = __expf(s[jj] - mval);
            l += p;
            ull p2v = pack2(p, p);
            const ulonglong2* vr = (const ulonglong2*)(sV + (j0 + jj) * 48);
            #pragma unroll
            for (int i = 0; i < 12; i++) {
                ulonglong2 vv = vr[i];
                O2[2*i]   = ffma2(p2v, vv.x, O2[2*i]);
                O2[2*i+1] = ffma2(p2v, vv.y, O2[2*i+1]);
            }
        }
    }
    {
        float inv = 1.f / l;
        ull iv2 = pack2(inv, inv);
        #pragma unroll
        for (int i = 0; i < 24; i++) O2[i] = fmul2(O2[i], iv2);
    }
    {
        int Hd = br ? 7 : 56;
        int Wd = br ? 56 : 7;
        int h = t / Wd, w = t - (t / Wd) * Wd;
        #pragma unroll
        for (int dy = -1; dy <= 1; dy++) {
            int hh = h + dy;
            if (hh < 0 || hh >= Hd) continue;
            #pragma unroll
            for (int dx = -1; dx <= 1; dx++) {
                int ww = w + dx;
                if (ww < 0 || ww >= Wd) continue;
                int tp = hh * Wd + ww;
                int nb = (dy + 1) * 3 + (dx + 1);
                const ulonglong2* vr = (const ulonglong2*)(sV + tp * 48);
                const ulonglong2* wr = (const ulonglong2*)(sw + nb * 48);
                #pragma unroll
                for (int i = 0; i < 12; i++) {
                    ulonglong2 vv = vr[i];
                    ulonglong2 wv = wr[i];
                    O2[2*i]   = ffma2(wv.x, vv.x, O2[2*i]);
                    O2[2*i+1] = ffma2(wv.y, vv.y, O2[2*i+1]);
                }
            }
        }
    }
    float* op = out + ((size_t)(b * DIMF + colq)) * NTOK + node;
    #pragma unroll
    for (int i = 0; i < 24; i++) {
        float2 u = unpack2(O2[i]);
        op[(size_t)(2*i)     * NTOK] = u.x + sb[2*i];
        op[(size_t)(2*i + 1) * NTOK] = u.y + sb[2*i + 1];
    }
}

// ---------------------------------------------------------------------------
// Lower-line flash attention, split-d query pairing.
// Lane pair (t, t^1): 2 queries jointly; each lane holds half the 64 dims.
// Halves smem LDS traffic per FMA (L1 writeback was the R3 bottleneck).
// ---------------------------------------------------------------------------
#define FBC 98
__global__ __launch_bounds__(64) void flash_dn_kernel(float* __restrict__ out)
{
    extern __shared__ float smem[];
    float* sK = smem;                 // [98][64]
    float* sV = smem + FBC * 64;      // [98][64]
    int tid  = threadIdx.x;
    int half = tid & 1;               // which 32-dim half this lane owns
    int pr   = tid >> 1;              // query-pair index within block (0..31)
    int qb = blockIdx.x;              // 0..48
    int hd = blockIdx.y;              // 0..2
    int b  = blockIdx.z;              // 0..3
    int qrow0 = qb * 64 + pr * 2;     // first of the 2 queries
    int colq  = 576 + hd * 64 + half * 32;

    const float scale = 0.125f;
    ull s2 = pack2(scale, scale);
    ull q2[2][16];
    #pragma unroll
    for (int qq = 0; qq < 2; qq++) {
        const ulonglong2* qp =
            (const ulonglong2*)(g_qkv + (size_t)(b * NTOK + qrow0 + qq) * 1152 + colq);
        #pragma unroll
        for (int i = 0; i < 8; i++) {
            ulonglong2 v = qp[i];
            q2[qq][2*i]   = fmul2(v.x, s2);
            q2[qq][2*i+1] = fmul2(v.y, s2);
        }
    }
    ull O2[2][16];
    #pragma unroll
    for (int qq = 0; qq < 2; qq++)
        #pragma unroll
        for (int i = 0; i < 16; i++) O2[qq][i] = 0ull;
    float m0 = -1e30f, m1 = -1e30f, l0 = 0.f, l1 = 0.f;

    for (int kt = 0; kt < NTOK / FBC; kt++) {
        __syncthreads();
        for (int idx = tid; idx < FBC * 16; idx += 64) {
            int r = idx >> 4, c4 = idx & 15;
            const float* base = g_qkv + (size_t)(b * NTOK + kt * FBC + r) * 1152 + 576 + hd * 64;
            ((float4*)(sK + r * 64))[c4] = ((const float4*)(base + TDF))[c4];
            ((float4*)(sV + r * 64))[c4] = ((const float4*)(base + 2 * TDF))[c4];
        }
        __syncthreads();

        for (int j0 = 0; j0 < FBC; j0 += 7) {
            float s0[7], s1[7];
            #pragma unroll
            for (int jj = 0; jj < 7; jj++) {
                const ulonglong2* kr =
                    (const ulonglong2*)(sK + (j0 + jj) * 64 + half * 32);
                ull a0 = 0ull, a1 = 0ull;
                #pragma unroll
                for (int i = 0; i < 8; i++) {
                    ulonglong2 kv = kr[i];
                    a0 = ffma2(q2[0][2*i],   kv.x, a0);
                    a0 = ffma2(q2[0][2*i+1], kv.y, a0);
                    a1 = ffma2(q2[1][2*i],   kv.x, a1);
                    a1 = ffma2(q2[1][2*i+1], kv.y, a1);
                }
                float2 u0 = unpack2(a0);
                float2 u1 = unpack2(a1);
                float p0 = u0.x + u0.y;
                float p1 = u1.x + u1.y;
                // add partner lane's half-dim partial
                s0[jj] = p0 + __shfl_xor_sync(0xFFFFFFFFu, p0, 1);
                s1[jj] = p1 + __shfl_xor_sync(0xFFFFFFFFu, p1, 1);
            }
            float cm0 = s0[0], cm1 = s1[0];
            #pragma unroll
            for (int jj = 1; jj < 7; jj++) {
                cm0 = fmaxf(cm0, s0[jj]);
                cm1 = fmaxf(cm1, s1[jj]);
            }
            if (cm0 > m0) {
                float corr = __expf(m0 - cm0);
                ull c2 = pack2(corr, corr);
                l0 *= corr;
                #pragma unroll
                for (int i = 0; i < 16; i++) O2[0][i] = fmul2(O2[0][i], c2);
                m0 = cm0;
            }
            if (cm1 > m1) {
                float corr = __expf(m1 - cm1);
                ull c2 = pack2(corr, corr);
                l1 *= corr;
                #pragma unroll
                for (int i = 0; i < 16; i++) O2[1][i] = fmul2(O2[1][i], c2);
                m1 = cm1;
            }
            #pragma unroll
            for (int jj = 0; jj < 7; jj++) {
                float p0 = __expf(s0[jj] - m0);
                float p1 = __expf(s1[jj] - m1);
                l0 += p0; l1 += p1;
                ull p02 = pack2(p0, p0);
                ull p12 = pack2(p1, p1);
                const ulonglong2* vr =
                    (const ulonglong2*)(sV + (j0 + jj) * 64 + half * 32);
                #pragma unroll
                for (int i = 0; i < 8; i++) {
                    ulonglong2 vv = vr[i];
                    O2[0][2*i]   = ffma2(p02, vv.x, O2[0][2*i]);
                    O2[0][2*i+1] = ffma2(p02, vv.y, O2[0][2*i+1]);
                    O2[1][2*i]   = ffma2(p12, vv.x, O2[1][2*i]);
                    O2[1][2*i+1] = ffma2(p12, vv.y, O2[1][2*i+1]);
                }
            }
        }
    }
    float inv0 = 1.f / l0, inv1 = 1.f / l1;
    ull iv0 = pack2(inv0, inv0), iv1 = pack2(inv1, inv1);
    // thread writes its half-dims for both queries
    float* opb = out + ((size_t)(b * DIMF + TDF + hd * 64 + half * 32)) * NTOK;
    #pragma unroll
    for (int i = 0; i < 16; i++) {
        float2 u0 = unpack2(fmul2(O2[0][i], iv0));
        float2 u1 = unpack2(fmul2(O2[1][i], iv1));
        opb[(size_t)(2*i)     * NTOK + qrow0]     = u0.x;
        opb[(size_t)(2*i + 1) * NTOK + qrow0]     = u0.y;
        opb[(size_t)(2*i)     * NTOK + qrow0 + 1] = u1.x;
        opb[(size_t)(2*i + 1) * NTOK + qrow0 + 1] = u1.y;
    }
}

// ---------------------------------------------------------------------------
extern "C" void kernel_launch(void* const* d_in, const int* in_sizes, int n_in,
                              void* d_out, int out_size)
{
    const float* xa  = (const float*)d_in[0];
    const float* p1  = (const float*)d_in[1];
    const float* p2  = (const float*)d_in[2];
    const float* wu  = (const float*)d_in[3];
    const float* wd  = (const float*)d_in[4];
    const float* lw0 = (const float*)d_in[5];
    const float* lb0 = (const float*)d_in[6];
    const float* lw1 = (const float*)d_in[7];
    const float* lb1 = (const float*)d_in[8];
    float* out = (float*)d_out;

    const int cswin_smem = (2 * 392 * 48 + 9 * 48 + 48) * 4;   // 152448 B
    const int flash_smem = FBC * 128 * 4;                      // 50176 B
    cudaFuncSetAttribute(cswin_kernel,
                         cudaFuncAttributeMaxDynamicSharedMemorySize, cswin_smem);
    cudaFuncSetAttribute(flash_dn_kernel,
                         cudaFuncAttributeMaxDynamicSharedMemorySize, flash_smem);

    gemm1_kernel<<<dim3(MTOT / 256, DIMF / 64), 256>>>(xa, p1, p2);
    gemm2_kernel<<<dim3(MTOT / 256, 1152 / 64), 256>>>(wu, wd);
    cswin_kernel<<<dim3(32, 2, 2), 416, cswin_smem>>>(lw0, lb0, lw1, lb1, out);
    flash_dn_kernel<<<dim3(NTOK / 64, 3, NB), 64, flash_smem>>>(out);
}

// round 9
// speedup vs baseline: 1.3611x; 1.3611x over previous
#include <cuda_runtime.h>
#include <math.h>

#define NB    4
#define NRES  56
#define NTOK  3136            // 56*56
#define DIMF  384
#define TDF   192
#define MTOT  12544           // NB*NTOK

typedef unsigned long long ull;

// packed f32x2 helpers (sm_100+ PTX; FFMA2 is PTX-only per SASS_QUICKREF)
__device__ __forceinline__ ull ffma2(ull a, ull b, ull c) {
    ull d; asm("fma.rn.f32x2 %0, %1, %2, %3;" : "=l"(d) : "l"(a), "l"(b), "l"(c)); return d;
}
__device__ __forceinline__ ull fmul2(ull a, ull b) {
    ull d; asm("mul.rn.f32x2 %0, %1, %2;" : "=l"(d) : "l"(a), "l"(b)); return d;
}
__device__ __forceinline__ ull pack2(float x, float y) {
    ull r; asm("mov.b64 %0, {%1, %2};" : "=l"(r) : "f"(x), "f"(y)); return r;
}
__device__ __forceinline__ float2 unpack2(ull v) {
    float2 r; asm("mov.b64 {%0, %1}, %2;" : "=f"(r.x), "=f"(r.y) : "l"(v)); return r;
}

// scratch (allocation-free rule: __device__ globals)
__device__ __align__(16) float g_tmp[(size_t)MTOT * DIMF];    // (m,384): 0..191 up, 192..383 dn
__device__ __align__(16) float g_qkv[(size_t)MTOT * 1152];    // (m,1152): 0..575 up qkv, 576..1151 dn qkv
__device__ __align__(16) float g_qT[(size_t)12 * 64 * NTOK];  // [(b*3+hd)][d][tok], pre-scaled Q_dn
__device__ __align__(16) float g_kT[(size_t)12 * 64 * NTOK];  // [(b*3+hd)][d][tok], K_dn

// ---------------------------------------------------------------------------
// GEMM1 (unchanged from R3 passing kernel)
// ---------------------------------------------------------------------------
__global__ __launch_bounds__(256) void gemm1_kernel(
    const float* __restrict__ xa, const float* __restrict__ p1,
    const float* __restrict__ p2)
{
    __shared__ __align__(16) float As[16][260];
    __shared__ __align__(16) float Bs[16][68];
    int tid = threadIdx.x;
    int m0 = blockIdx.x * 256;
    int o0 = blockIdx.y * 64;
    const float* wb = (o0 < TDF) ? p1 : p2;
    int orow0 = (o0 < TDF) ? o0 : (o0 - TDF);

    int mm = m0 + tid;
    int bb = mm / NTOK;
    int nn = mm - bb * NTOK;
    const float* asrc = xa + (size_t)bb * DIMF * NTOK + nn;

    int b_ol = tid >> 2;
    int b_kq = tid & 3;

    ull acc2[8][4];
    #pragma unroll
    for (int i = 0; i < 8; i++)
        #pragma unroll
        for (int j = 0; j < 4; j++) acc2[i][j] = 0ull;

    int mr = (tid >> 4) * 16;
    int oc = (tid & 15) * 4;

    for (int k0 = 0; k0 < DIMF; k0 += 16) {
        #pragma unroll
        for (int k = 0; k < 16; k++)
            As[k][tid] = asrc[(size_t)(k0 + k) * NTOK];
        {
            float4 w4 = *(const float4*)(wb + (size_t)(orow0 + b_ol) * DIMF + k0 + b_kq * 4);
            Bs[b_kq*4+0][b_ol] = w4.x;
            Bs[b_kq*4+1][b_ol] = w4.y;
            Bs[b_kq*4+2][b_ol] = w4.z;
            Bs[b_kq*4+3][b_ol] = w4.w;
        }
        __syncthreads();
        #pragma unroll
        for (int k = 0; k < 16; k++) {
            const ulonglong2* ap = (const ulonglong2*)&As[k][mr];
            ull a2[8];
            #pragma unroll
            for (int q = 0; q < 4; q++) {
                ulonglong2 t = ap[q];
                a2[2*q] = t.x; a2[2*q+1] = t.y;
            }
            float4 bv = *(const float4*)&Bs[k][oc];
            ull b2[4];
            b2[0] = pack2(bv.x, bv.x); b2[1] = pack2(bv.y, bv.y);
            b2[2] = pack2(bv.z, bv.z); b2[3] = pack2(bv.w, bv.w);
            #pragma unroll
            for (int i = 0; i < 8; i++)
                #pragma unroll
                for (int j = 0; j < 4; j++)
                    acc2[i][j] = ffma2(a2[i], b2[j], acc2[i][j]);
        }
        __syncthreads();
    }
    #pragma unroll
    for (int i = 0; i < 8; i++) {
        float2 u0 = unpack2(acc2[i][0]);
        float2 u1 = unpack2(acc2[i][1]);
        float2 u2 = unpack2(acc2[i][2]);
        float2 u3 = unpack2(acc2[i][3]);
        *(float4*)(g_tmp + (size_t)(m0 + mr + 2*i)     * DIMF + o0 + oc) = make_float4(u0.x, u1.x, u2.x, u3.x);
        *(float4*)(g_tmp + (size_t)(m0 + mr + 2*i + 1) * DIMF + o0 + oc) = make_float4(u0.y, u1.y, u2.y, u3.y);
    }
}

// ---------------------------------------------------------------------------
// GEMM2 (unchanged)
// ---------------------------------------------------------------------------
__global__ __launch_bounds__(256) void gemm2_kernel(
    const float* __restrict__ wu, const float* __restrict__ wd)
{
    __shared__ __align__(16) float As[16][260];
    __shared__ __align__(16) float Bs[16][68];
    int tid = threadIdx.x;
    int m0 = blockIdx.x * 256;
    int o0 = blockIdx.y * 64;
    const float* wb; int orow0, koff;
    if (o0 < 576) { wb = wu; orow0 = o0;       koff = 0;   }
    else          { wb = wd; orow0 = o0 - 576; koff = TDF; }

    int b_ol = tid >> 2;
    int b_kq = tid & 3;

    ull acc2[8][4];
    #pragma unroll
    for (int i = 0; i < 8; i++)
        #pragma unroll
        for (int j = 0; j < 4; j++) acc2[i][j] = 0ull;

    int mr = (tid >> 4) * 16;
    int oc = (tid & 15) * 4;
    const float* asrc = g_tmp + (size_t)(m0 + tid) * DIMF + koff;

    for (int k0 = 0; k0 < TDF; k0 += 16) {
        #pragma unroll
        for (int q = 0; q < 4; q++) {
            float4 a4 = *(const float4*)(asrc + k0 + q * 4);
            As[q*4+0][tid] = a4.x;
            As[q*4+1][tid] = a4.y;
            As[q*4+2][tid] = a4.z;
            As[q*4+3][tid] = a4.w;
        }
        {
            float4 w4 = *(const float4*)(wb + (size_t)(orow0 + b_ol) * TDF + k0 + b_kq * 4);
            Bs[b_kq*4+0][b_ol] = w4.x;
            Bs[b_kq*4+1][b_ol] = w4.y;
            Bs[b_kq*4+2][b_ol] = w4.z;
            Bs[b_kq*4+3][b_ol] = w4.w;
        }
        __syncthreads();
        #pragma unroll
        for (int k = 0; k < 16; k++) {
            const ulonglong2* ap = (const ulonglong2*)&As[k][mr];
            ull a2[8];
            #pragma unroll
            for (int q = 0; q < 4; q++) {
                ulonglong2 t = ap[q];
                a2[2*q] = t.x; a2[2*q+1] = t.y;
            }
            float4 bv = *(const float4*)&Bs[k][oc];
            ull b2[4];
            b2[0] = pack2(bv.x, bv.x); b2[1] = pack2(bv.y, bv.y);
            b2[2] = pack2(bv.z, bv.z); b2[3] = pack2(bv.w, bv.w);
            #pragma unroll
            for (int i = 0; i < 8; i++)
                #pragma unroll
                for (int j = 0; j < 4; j++)
                    acc2[i][j] = ffma2(a2[i], b2[j], acc2[i][j]);
        }
        __syncthreads();
    }
    #pragma unroll
    for (int i = 0; i < 8; i++) {
        float2 u0 = unpack2(acc2[i][0]);
        float2 u1 = unpack2(acc2[i][1]);
        float2 u2 = unpack2(acc2[i][2]);
        float2 u3 = unpack2(acc2[i][3]);
        *(float4*)(g_qkv + (size_t)(m0 + mr + 2*i)     * 1152 + o0 + oc) = make_float4(u0.x, u1.x, u2.x, u3.x);
        *(float4*)(g_qkv + (size_t)(m0 + mr + 2*i + 1) * 1152 + o0 + oc) = make_float4(u0.y, u1.y, u2.y, u3.y);
    }
}

// ---------------------------------------------------------------------------
// ktrans: build transposed (and Q pre-scaled) lower-line Q/K:
//   g_qT[(b*3+hd)][d][tok] = q_dn * 0.125 ; g_kT likewise (unscaled).
// ---------------------------------------------------------------------------
__global__ __launch_bounds__(256) void ktrans_kernel()
{
    int task = blockIdx.x * 256 + threadIdx.x;   // 12*16*3136 = 602112 total
    int tok = task % NTOK;
    int r   = task / NTOK;    // 0..191
    int d4  = r & 15;
    int bh  = r >> 4;         // 0..11
    int b   = bh / 3;
    int hd  = bh - b * 3;

    const float* src = g_qkv + (size_t)(b * NTOK + tok) * 1152 + 576 + hd * 64 + d4 * 4;
    float4 q4 = *(const float4*)src;            // Q_dn
    float4 k4 = *(const float4*)(src + TDF);    // K_dn
    size_t obase = ((size_t)bh * 64 + d4 * 4) * NTOK + tok;
    g_qT[obase + 0*NTOK] = q4.x * 0.125f;
    g_qT[obase + 1*NTOK] = q4.y * 0.125f;
    g_qT[obase + 2*NTOK] = q4.z * 0.125f;
    g_qT[obase + 3*NTOK] = q4.w * 0.125f;
    g_kT[obase + 0*NTOK] = k4.x;
    g_kT[obase + 1*NTOK] = k4.y;
    g_kT[obase + 2*NTOK] = k4.z;
    g_kT[obase + 3*NTOK] = k4.w;
}

// ---------------------------------------------------------------------------
// CSWin attention + fused LePE (unchanged from R3 passing kernel).
// ---------------------------------------------------------------------------
__global__ __launch_bounds__(416, 1) void cswin_kernel(
    const float* __restrict__ lw0, const float* __restrict__ lb0,
    const float* __restrict__ lw1, const float* __restrict__ lb1,
    float* __restrict__ out)
{
    extern __shared__ float smem[];
    float* sK = smem;                    // [392][48]
    float* sV = smem + 392 * 48;         // [392][48]
    float* sw = smem + 2 * 392 * 48;     // [9][48]
    float* sb = sw + 9 * 48;             // [48]

    int tid = threadIdx.x;
    int g  = blockIdx.x;
    int hd = blockIdx.y;
    int br = blockIdx.z;
    int wi = g & 7, b = g >> 3;
    int colq = br * 96 + hd * 48;

    {
        const float* lw = br ? lw1 : lw0;
        const float* lb = br ? lb1 : lb0;
        for (int idx = tid; idx < 432; idx += 416) {
            int nb = idx / 48, c = idx - nb * 48;
            sw[idx] = lw[(hd * 48 + c) * 9 + nb];
        }
        if (tid < 48) sb[tid] = lb[hd * 48 + tid];
    }
    for (int idx = tid; idx < 392 * 12; idx += 416) {
        int j = idx / 12, c4 = idx - j * 12;
        int node = (br == 0) ? ((j / 7) * NRES + wi * 7 + (j % 7)) : (wi * 392 + j);
        const float* base = g_qkv + (size_t)(b * NTOK + node) * 1152 + colq;
        ((float4*)(sK + j * 48))[c4] = ((const float4*)(base + TDF))[c4];
        ((float4*)(sV + j * 48))[c4] = ((const float4*)(base + 2 * TDF))[c4];
    }
    __syncthreads();
    if (tid >= 392) return;

    int t = tid;
    int node = (br == 0) ? ((t / 7) * NRES + wi * 7 + (t % 7)) : (wi * 392 + t);

    const float scale = 0.14433756729740643f;   // 1/sqrt(48)
    ull s2 = pack2(scale, scale);
    ull q2[24];
    {
        const ulonglong2* qp = (const ulonglong2*)(g_qkv + (size_t)(b * NTOK + node) * 1152 + colq);
        #pragma unroll
        for (int i = 0; i < 12; i++) {
            ulonglong2 v = qp[i];
            q2[2*i]   = fmul2(v.x, s2);
            q2[2*i+1] = fmul2(v.y, s2);
        }
    }
    ull O2[24];
    #pragma unroll
    for (int i = 0; i < 24; i++) O2[i] = 0ull;
    float mval = -1e30f, l = 0.f;

    for (int j0 = 0; j0 < 392; j0 += 8) {
        float s[8];
        #pragma unroll
        for (int jj = 0; jj < 8; jj++) {
            const ulonglong2* kr = (const ulonglong2*)(sK + (j0 + jj) * 48);
            ull acc = 0ull;
            #pragma unroll
            for (int i = 0; i < 12; i++) {
                ulonglong2 kv = kr[i];
                acc = ffma2(q2[2*i],   kv.x, acc);
                acc = ffma2(q2[2*i+1], kv.y, acc);
            }
            float2 u = unpack2(acc);
            s[jj] = u.x + u.y;
        }
        float cm = s[0];
        #pragma unroll
        for (int jj = 1; jj < 8; jj++) cm = fmaxf(cm, s[jj]);
        if (cm > mval) {
            float corr = __expf(mval - cm);
            ull c2 = pack2(corr, corr);
            l *= corr;
            #pragma unroll
            for (int i = 0; i < 24; i++) O2[i] = fmul2(O2[i], c2);
            mval = cm;
        }
        #pragma unroll
        for (int jj = 0; jj < 8; jj++) {
            float p = __expf(s[jj] - mval);
            l += p;
            ull p2v = pack2(p, p);
            const ulonglong2* vr = (const ulonglong2*)(sV + (j0 + jj) * 48);
            #pragma unroll
            for (int i = 0; i < 12; i++) {
                ulonglong2 vv = vr[i];
                O2[2*i]   = ffma2(p2v, vv.x, O2[2*i]);
                O2[2*i+1] = ffma2(p2v, vv.y, O2[2*i+1]);
            }
        }
    }
    {
        float inv = 1.f / l;
        ull iv2 = pack2(inv, inv);
        #pragma unroll
        for (int i = 0; i < 24; i++) O2[i] = fmul2(O2[i], iv2);
    }
    {
        int Hd = br ? 7 : 56;
        int Wd = br ? 56 : 7;
        int h = t / Wd, w = t - (t / Wd) * Wd;
        #pragma unroll
        for (int dy = -1; dy <= 1; dy++) {
            int hh = h + dy;
            if (hh < 0 || hh >= Hd) continue;
            #pragma unroll
            for (int dx = -1; dx <= 1; dx++) {
                int ww = w + dx;
                if (ww < 0 || ww >= Wd) continue;
                int tp = hh * Wd + ww;
                int nb = (dy + 1) * 3 + (dx + 1);
                const ulonglong2* vr = (const ulonglong2*)(sV + tp * 48);
                const ulonglong2* wr = (const ulonglong2*)(sw + nb * 48);
                #pragma unroll
                for (int i = 0; i < 12; i++) {
                    ulonglong2 vv = vr[i];
                    ulonglong2 wv = wr[i];
                    O2[2*i]   = ffma2(wv.x, vv.x, O2[2*i]);
                    O2[2*i+1] = ffma2(wv.y, vv.y, O2[2*i+1]);
                }
            }
        }
    }
    float* op = out + ((size_t)(b * DIMF + colq)) * NTOK + node;
    #pragma unroll
    for (int i = 0; i < 24; i++) {
        float2 u = unpack2(O2[i]);
        op[(size_t)(2*i)     * NTOK] = u.x + sb[2*i];
        op[(size_t)(2*i + 1) * NTOK] = u.y + sb[2*i + 1];
    }
}

// ---------------------------------------------------------------------------
// Lower-line flash attention v3: two-GEMM tiled, 8x8 micro-tiles.
// Br=64 queries/block, Bc=64 keys/tile, 64 threads (8x8 grid).
// P^T reuses the K buffer. smem 52KB -> 4 blocks/SM, grid 588 = one wave.
// ---------------------------------------------------------------------------
#define FP 68   // smem row pitch (floats)
__global__ __launch_bounds__(64) void flash_dn_kernel(float* __restrict__ out)
{
    extern __shared__ float smem[];
    float* Qt = smem;               // [64 d][FP]  Qt[d][q], pre-scaled
    float* KP = smem + 64 * FP;     // [64][FP]    Kt[d][key], then Pt[key][q]
    float* Vs = smem + 128 * FP;    // [64][FP]    Vs[key][d]

    int tid = threadIdx.x;
    int tq = tid >> 3;      // 0..7
    int tk = tid & 7;       // 0..7
    int qb = blockIdx.x;    // 0..48
    int hd = blockIdx.y;    // 0..2
    int b  = blockIdx.z;    // 0..3
    int q0 = qb * 64;
    int bh = b * 3 + hd;
    const float* qTsrc = g_qT + (size_t)bh * 64 * NTOK;
    const float* kTsrc = g_kT + (size_t)bh * 64 * NTOK;

    // prologue: Q tile [64d][64q] (already transposed + scaled in gmem)
    #pragma unroll
    for (int i = 0; i < 16; i++) {
        int task = i * 64 + tid;
        int row = task >> 4, c4 = task & 15;
        *(float4*)&Qt[row * FP + c4 * 4] =
            *(const float4*)(qTsrc + (size_t)row * NTOK + q0 + c4 * 4);
    }

    ull O2[4][8];                 // [qpair][dcol]
    #pragma unroll
    for (int p = 0; p < 4; p++)
        #pragma unroll
        for (int d = 0; d < 8; d++) O2[p][d] = 0ull;
    float m[8], l[8];
    #pragma unroll
    for (int r = 0; r < 8; r++) { m[r] = -1e30f; l[r] = 0.f; }

    for (int kt = 0; kt < NTOK / 64; kt++) {
        int k0 = kt * 64;
        __syncthreads();   // prior tile's reads of KP/Vs complete (also covers prologue)
        #pragma unroll
        for (int i = 0; i < 16; i++) {
            int task = i * 64 + tid;
            int row = task >> 4, c4 = task & 15;
            *(float4*)&KP[row * FP + c4 * 4] =
                *(const float4*)(kTsrc + (size_t)row * NTOK + k0 + c4 * 4);
            *(float4*)&Vs[row * FP + c4 * 4] =
                *(const float4*)(g_qkv + (size_t)(b * NTOK + k0 + row) * 1152 + 960 + hd * 64 + c4 * 4);
        }
        __syncthreads();

        // ---- S-GEMM: s2[qpair][key] over d ----
        ull s2[4][8];
        #pragma unroll
        for (int p = 0; p < 4; p++)
            #pragma unroll
            for (int kk = 0; kk < 8; kk++) s2[p][kk] = 0ull;
        #pragma unroll 4
        for (int k = 0; k < 64; k++) {
            ulonglong2 aa = *(const ulonglong2*)&Qt[k * FP + tq * 8];
            ulonglong2 ab = *(const ulonglong2*)&Qt[k * FP + tq * 8 + 4];
            ull a2[4] = {aa.x, aa.y, ab.x, ab.y};
            float4 b0 = *(const float4*)&KP[k * FP + tk * 8];
            float4 b1 = *(const float4*)&KP[k * FP + tk * 8 + 4];
            float bk[8] = {b0.x, b0.y, b0.z, b0.w, b1.x, b1.y, b1.z, b1.w};
            #pragma unroll
            for (int kk = 0; kk < 8; kk++) {
                ull bb = pack2(bk[kk], bk[kk]);
                #pragma unroll
                for (int p = 0; p < 4; p++)
                    s2[p][kk] = ffma2(a2[p], bb, s2[p][kk]);
            }
        }

        // ---- softmax (registers) ----
        float s[8][8];
        #pragma unroll
        for (int p = 0; p < 4; p++)
            #pragma unroll
            for (int kk = 0; kk < 8; kk++) {
                float2 u = unpack2(s2[p][kk]);
                s[2*p][kk] = u.x; s[2*p+1][kk] = u.y;
            }
        float corr[8];
        #pragma unroll
        for (int r = 0; r < 8; r++) {
            float mx = s[r][0];
            #pragma unroll
            for (int kk = 1; kk < 8; kk++) mx = fmaxf(mx, s[r][kk]);
            mx = fmaxf(mx, __shfl_xor_sync(0xFFFFFFFFu, mx, 1));
            mx = fmaxf(mx, __shfl_xor_sync(0xFFFFFFFFu, mx, 2));
            mx = fmaxf(mx, __shfl_xor_sync(0xFFFFFFFFu, mx, 4));
            float mn = fmaxf(m[r], mx);
            corr[r] = __expf(m[r] - mn);
            m[r] = mn;
            float sum = 0.f;
            #pragma unroll
            for (int kk = 0; kk < 8; kk++) {
                float p = __expf(s[r][kk] - mn);
                s[r][kk] = p;
                sum += p;
            }
            sum += __shfl_xor_sync(0xFFFFFFFFu, sum, 1);
            sum += __shfl_xor_sync(0xFFFFFFFFu, sum, 2);
            sum += __shfl_xor_sync(0xFFFFFFFFu, sum, 4);
            l[r] = l[r] * corr[r] + sum;
        }
        #pragma unroll
        for (int p = 0; p < 4; p++) {
            ull c2 = pack2(corr[2*p], corr[2*p+1]);
            #pragma unroll
            for (int d = 0; d < 8; d++) O2[p][d] = fmul2(O2[p][d], c2);
        }

        __syncthreads();   // all lanes done reading KP as K
        // write P^T[key][q] into KP
        #pragma unroll
        for (int kk = 0; kk < 8; kk++) {
            int key = tk * 8 + kk;
            *(float4*)&KP[key * FP + tq * 8] =
                make_float4(s[0][kk], s[1][kk], s[2][kk], s[3][kk]);
            *(float4*)&KP[key * FP + tq * 8 + 4] =
                make_float4(s[4][kk], s[5][kk], s[6][kk], s[7][kk]);
        }
        __syncthreads();

        // ---- PV-GEMM: O2[qpair][d] over keys ----
        #pragma unroll 4
        for (int key = 0; key < 64; key++) {
            ulonglong2 aa = *(const ulonglong2*)&KP[key * FP + tq * 8];
            ulonglong2 ab = *(const ulonglong2*)&KP[key * FP + tq * 8 + 4];
            ull a2[4] = {aa.x, aa.y, ab.x, ab.y};
            float4 v0 = *(const float4*)&Vs[key * FP + tk * 8];
            float4 v1 = *(const float4*)&Vs[key * FP + tk * 8 + 4];
            float bv[8] = {v0.x, v0.y, v0.z, v0.w, v1.x, v1.y, v1.z, v1.w};
            #pragma unroll
            for (int d = 0; d < 8; d++) {
                ull bb = pack2(bv[d], bv[d]);
                #pragma unroll
                for (int p = 0; p < 4; p++)
                    O2[p][d] = ffma2(a2[p], bb, O2[p][d]);
            }
        }
    }

    // final: normalize + store
    #pragma unroll
    for (int p = 0; p < 4; p++) {
        ull iv2 = pack2(1.f / l[2*p], 1.f / l[2*p+1]);
        #pragma unroll
        for (int d = 0; d < 8; d++) O2[p][d] = fmul2(O2[p][d], iv2);
    }
    #pragma unroll
    for (int d = 0; d < 8; d++) {
        int ch = TDF + hd * 64 + tk * 8 + d;
        float o[8];
        #pragma unroll
        for (int p = 0; p < 4; p++) {
            float2 u = unpack2(O2[p][d]);
            o[2*p] = u.x; o[2*p+1] = u.y;
        }
        float* dst = out + ((size_t)(b * DIMF + ch)) * NTOK + q0 + tq * 8;
        *(float4*)dst       = make_float4(o[0], o[1], o[2], o[3]);
        *(float4*)(dst + 4) = make_float4(o[4], o[5], o[6], o[7]);
    }
}

// ---------------------------------------------------------------------------
extern "C" void kernel_launch(void* const* d_in, const int* in_sizes, int n_in,
                              void* d_out, int out_size)
{
    const float* xa  = (const float*)d_in[0];
    const float* p1  = (const float*)d_in[1];
    const float* p2  = (const float*)d_in[2];
    const float* wu  = (const float*)d_in[3];
    const float* wd  = (const float*)d_in[4];
    const float* lw0 = (const float*)d_in[5];
    const float* lb0 = (const float*)d_in[6];
    const float* lw1 = (const float*)d_in[7];
    const float* lb1 = (const float*)d_in[8];
    float* out = (float*)d_out;

    const int cswin_smem = (2 * 392 * 48 + 9 * 48 + 48) * 4;   // 152448 B
    const int flash_smem = 3 * 64 * FP * 4;                    // 52224 B
    cudaFuncSetAttribute(cswin_kernel,
                         cudaFuncAttributeMaxDynamicSharedMemorySize, cswin_smem);
    cudaFuncSetAttribute(flash_dn_kernel,
                         cudaFuncAttributeMaxDynamicSharedMemorySize, flash_smem);

    gemm1_kernel<<<dim3(MTOT / 256, DIMF / 64), 256>>>(xa, p1, p2);
    gemm2_kernel<<<dim3(MTOT / 256, 1152 / 64), 256>>>(wu, wd);
    ktrans_kernel<<<12 * 16 * NTOK / 256, 256>>>();
    cswin_kernel<<<dim3(32, 2, 2), 416, cswin_smem>>>(lw0, lb0, lw1, lb1, out);
    flash_dn_kernel<<<dim3(NTOK / 64, 3, NB), 64, flash_smem>>>(out);
}

// round 10
// speedup vs baseline: 1.3654x; 1.0032x over previous
#include <cuda_runtime.h>
#include <math.h>

#define NB    4
#define NRES  56
#define NTOK  3136            // 56*56
#define DIMF  384
#define TDF   192
#define MTOT  12544           // NB*NTOK

typedef unsigned long long ull;

// packed f32x2 helpers (sm_100+ PTX; FFMA2 is PTX-only per SASS_QUICKREF)
__device__ __forceinline__ ull ffma2(ull a, ull b, ull c) {
    ull d; asm("fma.rn.f32x2 %0, %1, %2, %3;" : "=l"(d) : "l"(a), "l"(b), "l"(c)); return d;
}
__device__ __forceinline__ ull fmul2(ull a, ull b) {
    ull d; asm("mul.rn.f32x2 %0, %1, %2;" : "=l"(d) : "l"(a), "l"(b)); return d;
}
__device__ __forceinline__ ull pack2(float x, float y) {
    ull r; asm("mov.b64 %0, {%1, %2};" : "=l"(r) : "f"(x), "f"(y)); return r;
}
__device__ __forceinline__ float2 unpack2(ull v) {
    float2 r; asm("mov.b64 {%0, %1}, %2;" : "=f"(r.x), "=f"(r.y) : "l"(v)); return r;
}
// exp2 approx (== __expf when logits are pre-scaled by log2(e))
__device__ __forceinline__ float exp2a(float x) {
    float y; asm("ex2.approx.ftz.f32 %0, %1;" : "=f"(y) : "f"(x)); return y;
}

// scratch (allocation-free rule: __device__ globals)
__device__ __align__(16) float g_tmp[(size_t)MTOT * DIMF];    // (m,384): 0..191 up, 192..383 dn
__device__ __align__(16) float g_qkv[(size_t)MTOT * 1152];    // (m,1152): 0..575 up qkv, 576..1151 dn qkv
__device__ __align__(16) float g_qT[(size_t)12 * 64 * NTOK];  // [(b*3+hd)][d][tok], pre-scaled Q_dn
__device__ __align__(16) float g_kT[(size_t)12 * 64 * NTOK];  // [(b*3+hd)][d][tok], K_dn

// ---------------------------------------------------------------------------
// GEMM1 (unchanged)
// ---------------------------------------------------------------------------
__global__ __launch_bounds__(256) void gemm1_kernel(
    const float* __restrict__ xa, const float* __restrict__ p1,
    const float* __restrict__ p2)
{
    __shared__ __align__(16) float As[16][260];
    __shared__ __align__(16) float Bs[16][68];
    int tid = threadIdx.x;
    int m0 = blockIdx.x * 256;
    int o0 = blockIdx.y * 64;
    const float* wb = (o0 < TDF) ? p1 : p2;
    int orow0 = (o0 < TDF) ? o0 : (o0 - TDF);

    int mm = m0 + tid;
    int bb = mm / NTOK;
    int nn = mm - bb * NTOK;
    const float* asrc = xa + (size_t)bb * DIMF * NTOK + nn;

    int b_ol = tid >> 2;
    int b_kq = tid & 3;

    ull acc2[8][4];
    #pragma unroll
    for (int i = 0; i < 8; i++)
        #pragma unroll
        for (int j = 0; j < 4; j++) acc2[i][j] = 0ull;

    int mr = (tid >> 4) * 16;
    int oc = (tid & 15) * 4;

    for (int k0 = 0; k0 < DIMF; k0 += 16) {
        #pragma unroll
        for (int k = 0; k < 16; k++)
            As[k][tid] = asrc[(size_t)(k0 + k) * NTOK];
        {
            float4 w4 = *(const float4*)(wb + (size_t)(orow0 + b_ol) * DIMF + k0 + b_kq * 4);
            Bs[b_kq*4+0][b_ol] = w4.x;
            Bs[b_kq*4+1][b_ol] = w4.y;
            Bs[b_kq*4+2][b_ol] = w4.z;
            Bs[b_kq*4+3][b_ol] = w4.w;
        }
        __syncthreads();
        #pragma unroll
        for (int k = 0; k < 16; k++) {
            const ulonglong2* ap = (const ulonglong2*)&As[k][mr];
            ull a2[8];
            #pragma unroll
            for (int q = 0; q < 4; q++) {
                ulonglong2 t = ap[q];
                a2[2*q] = t.x; a2[2*q+1] = t.y;
            }
            float4 bv = *(const float4*)&Bs[k][oc];
            ull b2[4];
            b2[0] = pack2(bv.x, bv.x); b2[1] = pack2(bv.y, bv.y);
            b2[2] = pack2(bv.z, bv.z); b2[3] = pack2(bv.w, bv.w);
            #pragma unroll
            for (int i = 0; i < 8; i++)
                #pragma unroll
                for (int j = 0; j < 4; j++)
                    acc2[i][j] = ffma2(a2[i], b2[j], acc2[i][j]);
        }
        __syncthreads();
    }
    #pragma unroll
    for (int i = 0; i < 8; i++) {
        float2 u0 = unpack2(acc2[i][0]);
        float2 u1 = unpack2(acc2[i][1]);
        float2 u2 = unpack2(acc2[i][2]);
        float2 u3 = unpack2(acc2[i][3]);
        *(float4*)(g_tmp + (size_t)(m0 + mr + 2*i)     * DIMF + o0 + oc) = make_float4(u0.x, u1.x, u2.x, u3.x);
        *(float4*)(g_tmp + (size_t)(m0 + mr + 2*i + 1) * DIMF + o0 + oc) = make_float4(u0.y, u1.y, u2.y, u3.y);
    }
}

// ---------------------------------------------------------------------------
// GEMM2 (unchanged)
// ---------------------------------------------------------------------------
__global__ __launch_bounds__(256) void gemm2_kernel(
    const float* __restrict__ wu, const float* __restrict__ wd)
{
    __shared__ __align__(16) float As[16][260];
    __shared__ __align__(16) float Bs[16][68];
    int tid = threadIdx.x;
    int m0 = blockIdx.x * 256;
    int o0 = blockIdx.y * 64;
    const float* wb; int orow0, koff;
    if (o0 < 576) { wb = wu; orow0 = o0;       koff = 0;   }
    else          { wb = wd; orow0 = o0 - 576; koff = TDF; }

    int b_ol = tid >> 2;
    int b_kq = tid & 3;

    ull acc2[8][4];
    #pragma unroll
    for (int i = 0; i < 8; i++)
        #pragma unroll
        for (int j = 0; j < 4; j++) acc2[i][j] = 0ull;

    int mr = (tid >> 4) * 16;
    int oc = (tid & 15) * 4;
    const float* asrc = g_tmp + (size_t)(m0 + tid) * DIMF + koff;

    for (int k0 = 0; k0 < TDF; k0 += 16) {
        #pragma unroll
        for (int q = 0; q < 4; q++) {
            float4 a4 = *(const float4*)(asrc + k0 + q * 4);
            As[q*4+0][tid] = a4.x;
            As[q*4+1][tid] = a4.y;
            As[q*4+2][tid] = a4.z;
            As[q*4+3][tid] = a4.w;
        }
        {
            float4 w4 = *(const float4*)(wb + (size_t)(orow0 + b_ol) * TDF + k0 + b_kq * 4);
            Bs[b_kq*4+0][b_ol] = w4.x;
            Bs[b_kq*4+1][b_ol] = w4.y;
            Bs[b_kq*4+2][b_ol] = w4.z;
            Bs[b_kq*4+3][b_ol] = w4.w;
        }
        __syncthreads();
        #pragma unroll
        for (int k = 0; k < 16; k++) {
            const ulonglong2* ap = (const ulonglong2*)&As[k][mr];
            ull a2[8];
            #pragma unroll
            for (int q = 0; q < 4; q++) {
                ulonglong2 t = ap[q];
                a2[2*q] = t.x; a2[2*q+1] = t.y;
            }
            float4 bv = *(const float4*)&Bs[k][oc];
            ull b2[4];
            b2[0] = pack2(bv.x, bv.x); b2[1] = pack2(bv.y, bv.y);
            b2[2] = pack2(bv.z, bv.z); b2[3] = pack2(bv.w, bv.w);
            #pragma unroll
            for (int i = 0; i < 8; i++)
                #pragma unroll
                for (int j = 0; j < 4; j++)
                    acc2[i][j] = ffma2(a2[i], b2[j], acc2[i][j]);
        }
        __syncthreads();
    }
    #pragma unroll
    for (int i = 0; i < 8; i++) {
        float2 u0 = unpack2(acc2[i][0]);
        float2 u1 = unpack2(acc2[i][1]);
        float2 u2 = unpack2(acc2[i][2]);
        float2 u3 = unpack2(acc2[i][3]);
        *(float4*)(g_qkv + (size_t)(m0 + mr + 2*i)     * 1152 + o0 + oc) = make_float4(u0.x, u1.x, u2.x, u3.x);
        *(float4*)(g_qkv + (size_t)(m0 + mr + 2*i + 1) * 1152 + o0 + oc) = make_float4(u0.y, u1.y, u2.y, u3.y);
    }
}

// ---------------------------------------------------------------------------
// ktrans: transposed (Q pre-scaled by 0.125*log2e for base-2 softmax) Q/K.
// ---------------------------------------------------------------------------
__global__ __launch_bounds__(256) void ktrans_kernel()
{
    int task = blockIdx.x * 256 + threadIdx.x;   // 602112 total
    int tok = task % NTOK;
    int r   = task / NTOK;    // 0..191
    int d4  = r & 15;
    int bh  = r >> 4;         // 0..11
    int b   = bh / 3;
    int hd  = bh - b * 3;

    const float qs = 0.18033688011112042f;   // 0.125 * log2(e)
    const float* src = g_qkv + (size_t)(b * NTOK + tok) * 1152 + 576 + hd * 64 + d4 * 4;
    float4 q4 = *(const float4*)src;            // Q_dn
    float4 k4 = *(const float4*)(src + TDF);    // K_dn
    size_t obase = ((size_t)bh * 64 + d4 * 4) * NTOK + tok;
    g_qT[obase + 0*NTOK] = q4.x * qs;
    g_qT[obase + 1*NTOK] = q4.y * qs;
    g_qT[obase + 2*NTOK] = q4.z * qs;
    g_qT[obase + 3*NTOK] = q4.w * qs;
    g_kT[obase + 0*NTOK] = k4.x;
    g_kT[obase + 1*NTOK] = k4.y;
    g_kT[obase + 2*NTOK] = k4.z;
    g_kT[obase + 3*NTOK] = k4.w;
}

// ---------------------------------------------------------------------------
// CSWin attention + fused LePE, v2: 2 queries per thread (196 compute threads
// of a 256-thread block). Halves broadcast-LDS per FMA (was L1-bound 2:1).
// Base-2 softmax (scale pre-multiplied by log2e).
// ---------------------------------------------------------------------------
__global__ __launch_bounds__(256, 1) void cswin_kernel(
    const float* __restrict__ lw0, const float* __restrict__ lb0,
    const float* __restrict__ lw1, const float* __restrict__ lb1,
    float* __restrict__ out)
{
    extern __shared__ float smem[];
    float* sK    = smem;                    // [392][48]
    float* sV    = smem + 392 * 48;         // [392][48]
    float* swt   = smem + 2 * 392 * 48;     // [9][48]
    float* sbias = swt + 9 * 48;            // [48]

    int tid = threadIdx.x;
    int g  = blockIdx.x;
    int hd = blockIdx.y;
    int br = blockIdx.z;
    int wi = g & 7, b = g >> 3;
    int colq = br * 96 + hd * 48;

    {
        const float* lw = br ? lw1 : lw0;
        const float* lb = br ? lb1 : lb0;
        for (int idx = tid; idx < 432; idx += 256) {
            int nb = idx / 48, c = idx - nb * 48;
            swt[idx] = lw[(hd * 48 + c) * 9 + nb];
        }
        if (tid < 48) sbias[tid] = lb[hd * 48 + tid];
    }
    for (int idx = tid; idx < 392 * 12; idx += 256) {
        int j = idx / 12, c4 = idx - j * 12;
        int node = (br == 0) ? ((j / 7) * NRES + wi * 7 + (j % 7)) : (wi * 392 + j);
        const float* base = g_qkv + (size_t)(b * NTOK + node) * 1152 + colq;
        ((float4*)(sK + j * 48))[c4] = ((const float4*)(base + TDF))[c4];
        ((float4*)(sV + j * 48))[c4] = ((const float4*)(base + 2 * TDF))[c4];
    }
    __syncthreads();
    if (tid >= 196) return;

    int t0 = tid * 2, t1 = t0 + 1;
    int node0 = (br == 0) ? ((t0 / 7) * NRES + wi * 7 + (t0 % 7)) : (wi * 392 + t0);
    int node1 = (br == 0) ? ((t1 / 7) * NRES + wi * 7 + (t1 % 7)) : (wi * 392 + t1);

    const float scale = 0.2082351129f;   // 48^-0.5 * log2(e)
    ull sc2 = pack2(scale, scale);
    ull qA[24], qB[24];
    {
        const ulonglong2* qp0 = (const ulonglong2*)(g_qkv + (size_t)(b * NTOK + node0) * 1152 + colq);
        const ulonglong2* qp1 = (const ulonglong2*)(g_qkv + (size_t)(b * NTOK + node1) * 1152 + colq);
        #pragma unroll
        for (int i = 0; i < 12; i++) {
            ulonglong2 v0 = qp0[i];
            ulonglong2 v1 = qp1[i];
            qA[2*i] = fmul2(v0.x, sc2); qA[2*i+1] = fmul2(v0.y, sc2);
            qB[2*i] = fmul2(v1.x, sc2); qB[2*i+1] = fmul2(v1.y, sc2);
        }
    }
    ull OA[24], OB[24];
    #pragma unroll
    for (int i = 0; i < 24; i++) { OA[i] = 0ull; OB[i] = 0ull; }
    float mA = -1e30f, mB = -1e30f, lA = 0.f, lB = 0.f;

    for (int j0 = 0; j0 < 392; j0 += 8) {
        float sA[8], sB[8];
        #pragma unroll
        for (int jj = 0; jj < 8; jj++) {
            const ulonglong2* kr = (const ulonglong2*)(sK + (j0 + jj) * 48);
            ull a0 = 0ull, a1 = 0ull;
            #pragma unroll
            for (int i = 0; i < 12; i++) {
                ulonglong2 kv = kr[i];
                a0 = ffma2(qA[2*i],   kv.x, a0);
                a0 = ffma2(qA[2*i+1], kv.y, a0);
                a1 = ffma2(qB[2*i],   kv.x, a1);
                a1 = ffma2(qB[2*i+1], kv.y, a1);
            }
            float2 u0 = unpack2(a0);
            float2 u1 = unpack2(a1);
            sA[jj] = u0.x + u0.y;
            sB[jj] = u1.x + u1.y;
        }
        float cA = sA[0], cB = sB[0];
        #pragma unroll
        for (int jj = 1; jj < 8; jj++) {
            cA = fmaxf(cA, sA[jj]);
            cB = fmaxf(cB, sB[jj]);
        }
        if (cA > mA) {
            float corr = exp2a(mA - cA);
            ull c2 = pack2(corr, corr);
            lA *= corr;
            #pragma unroll
            for (int i = 0; i < 24; i++) OA[i] = fmul2(OA[i], c2);
            mA = cA;
        }
        if (cB > mB) {
            float corr = exp2a(mB - cB);
            ull c2 = pack2(corr, corr);
            lB *= corr;
            #pragma unroll
            for (int i = 0; i < 24; i++) OB[i] = fmul2(OB[i], c2);
            mB = cB;
        }
        #pragma unroll
        for (int jj = 0; jj < 8; jj++) {
            float pA = exp2a(sA[jj] - mA);
            float pB = exp2a(sB[jj] - mB);
            lA += pA; lB += pB;
            ull pA2 = pack2(pA, pA);
            ull pB2 = pack2(pB, pB);
            const ulonglong2* vr = (const ulonglong2*)(sV + (j0 + jj) * 48);
            #pragma unroll
            for (int i = 0; i < 12; i++) {
                ulonglong2 vv = vr[i];
                OA[2*i]   = ffma2(pA2, vv.x, OA[2*i]);
                OA[2*i+1] = ffma2(pA2, vv.y, OA[2*i+1]);
                OB[2*i]   = ffma2(pB2, vv.x, OB[2*i]);
                OB[2*i+1] = ffma2(pB2, vv.y, OB[2*i+1]);
            }
        }
    }
    {   // normalize
        float ia = 1.f / lA, ib = 1.f / lB;
        ull iva = pack2(ia, ia), ivb = pack2(ib, ib);
        #pragma unroll
        for (int i = 0; i < 24; i++) {
            OA[i] = fmul2(OA[i], iva);
            OB[i] = fmul2(OB[i], ivb);
        }
    }
    {   // fused LePE for both queries (depthwise 3x3 SAME within window)
        int Hd = br ? 7 : 56;
        int Wd = br ? 56 : 7;
        #pragma unroll
        for (int qq = 0; qq < 2; qq++) {
            int t = qq ? t1 : t0;
            ull* O = qq ? OB : OA;
            int h = t / Wd, w = t - (t / Wd) * Wd;
            #pragma unroll
            for (int dy = -1; dy <= 1; dy++) {
                int hh = h + dy;
                if (hh < 0 || hh >= Hd) continue;
                #pragma unroll
                for (int dx = -1; dx <= 1; dx++) {
                    int ww = w + dx;
                    if (ww < 0 || ww >= Wd) continue;
                    int tp = hh * Wd + ww;
                    int nb = (dy + 1) * 3 + (dx + 1);
                    const ulonglong2* vr = (const ulonglong2*)(sV + tp * 48);
                    const ulonglong2* wr = (const ulonglong2*)(swt + nb * 48);
                    #pragma unroll
                    for (int i = 0; i < 12; i++) {
                        ulonglong2 vv = vr[i];
                        ulonglong2 wv = wr[i];
                        O[2*i]   = ffma2(wv.x, vv.x, O[2*i]);
                        O[2*i+1] = ffma2(wv.y, vv.y, O[2*i+1]);
                    }
                }
            }
        }
    }
    float* opA = out + ((size_t)(b * DIMF + colq)) * NTOK + node0;
    float* opB = out + ((size_t)(b * DIMF + colq)) * NTOK + node1;
    #pragma unroll
    for (int i = 0; i < 24; i++) {
        float2 uA = unpack2(OA[i]);
        float2 uB = unpack2(OB[i]);
        float b0 = sbias[2*i], b1 = sbias[2*i + 1];
        opA[(size_t)(2*i)     * NTOK] = uA.x + b0;
        opA[(size_t)(2*i + 1) * NTOK] = uA.y + b1;
        opB[(size_t)(2*i)     * NTOK] = uB.x + b0;
        opB[(size_t)(2*i + 1) * NTOK] = uB.y + b1;
    }
}

// ---------------------------------------------------------------------------
// Lower-line flash attention v3 (structure unchanged; exp -> ex2 with
// log2e folded into the ktrans Q pre-scale).
// ---------------------------------------------------------------------------
#define FP 68   // smem row pitch (floats)
__global__ __launch_bounds__(64) void flash_dn_kernel(float* __restrict__ out)
{
    extern __shared__ float smem[];
    float* Qt = smem;               // [64 d][FP]  Qt[d][q], pre-scaled
    float* KP = smem + 64 * FP;     // [64][FP]    Kt[d][key], then Pt[key][q]
    float* Vs = smem + 128 * FP;    // [64][FP]    Vs[key][d]

    int tid = threadIdx.x;
    int tq = tid >> 3;      // 0..7
    int tk = tid & 7;       // 0..7
    int qb = blockIdx.x;    // 0..48
    int hd = blockIdx.y;    // 0..2
    int b  = blockIdx.z;    // 0..3
    int q0 = qb * 64;
    int bh = b * 3 + hd;
    const float* qTsrc = g_qT + (size_t)bh * 64 * NTOK;
    const float* kTsrc = g_kT + (size_t)bh * 64 * NTOK;

    #pragma unroll
    for (int i = 0; i < 16; i++) {
        int task = i * 64 + tid;
        int row = task >> 4, c4 = task & 15;
        *(float4*)&Qt[row * FP + c4 * 4] =
            *(const float4*)(qTsrc + (size_t)row * NTOK + q0 + c4 * 4);
    }

    ull O2[4][8];                 // [qpair][dcol]
    #pragma unroll
    for (int p = 0; p < 4; p++)
        #pragma unroll
        for (int d = 0; d < 8; d++) O2[p][d] = 0ull;
    float m[8], l[8];
    #pragma unroll
    for (int r = 0; r < 8; r++) { m[r] = -1e30f; l[r] = 0.f; }

    for (int kt = 0; kt < NTOK / 64; kt++) {
        int k0 = kt * 64;
        __syncthreads();
        #pragma unroll
        for (int i = 0; i < 16; i++) {
            int task = i * 64 + tid;
            int row = task >> 4, c4 = task & 15;
            *(float4*)&KP[row * FP + c4 * 4] =
                *(const float4*)(kTsrc + (size_t)row * NTOK + k0 + c4 * 4);
            *(float4*)&Vs[row * FP + c4 * 4] =
                *(const float4*)(g_qkv + (size_t)(b * NTOK + k0 + row) * 1152 + 960 + hd * 64 + c4 * 4);
        }
        __syncthreads();

        // ---- S-GEMM ----
        ull s2[4][8];
        #pragma unroll
        for (int p = 0; p < 4; p++)
            #pragma unroll
            for (int kk = 0; kk < 8; kk++) s2[p][kk] = 0ull;
        #pragma unroll 4
        for (int k = 0; k < 64; k++) {
            ulonglong2 aa = *(const ulonglong2*)&Qt[k * FP + tq * 8];
            ulonglong2 ab = *(const ulonglong2*)&Qt[k * FP + tq * 8 + 4];
            ull a2[4] = {aa.x, aa.y, ab.x, ab.y};
            float4 b0 = *(const float4*)&KP[k * FP + tk * 8];
            float4 b1 = *(const float4*)&KP[k * FP + tk * 8 + 4];
            float bk[8] = {b0.x, b0.y, b0.z, b0.w, b1.x, b1.y, b1.z, b1.w};
            #pragma unroll
            for (int kk = 0; kk < 8; kk++) {
                ull bb = pack2(bk[kk], bk[kk]);
                #pragma unroll
                for (int p = 0; p < 4; p++)
                    s2[p][kk] = ffma2(a2[p], bb, s2[p][kk]);
            }
        }

        // ---- softmax (base-2) ----
        float s[8][8];
        #pragma unroll
        for (int p = 0; p < 4; p++)
            #pragma unroll
            for (int kk = 0; kk < 8; kk++) {
                float2 u = unpack2(s2[p][kk]);
                s[2*p][kk] = u.x; s[2*p+1][kk] = u.y;
            }
        float corr[8];
        #pragma unroll
        for (int r = 0; r < 8; r++) {
            float mx = s[r][0];
            #pragma unroll
            for (int kk = 1; kk < 8; kk++) mx = fmaxf(mx, s[r][kk]);
            mx = fmaxf(mx, __shfl_xor_sync(0xFFFFFFFFu, mx, 1));
            mx = fmaxf(mx, __shfl_xor_sync(0xFFFFFFFFu, mx, 2));
            mx = fmaxf(mx, __shfl_xor_sync(0xFFFFFFFFu, mx, 4));
            float mn = fmaxf(m[r], mx);
            corr[r] = exp2a(m[r] - mn);
            m[r] = mn;
            float sum = 0.f;
            #pragma unroll
            for (int kk = 0; kk < 8; kk++) {
                float p = exp2a(s[r][kk] - mn);
                s[r][kk] = p;
                sum += p;
            }
            sum += __shfl_xor_sync(0xFFFFFFFFu, sum, 1);
            sum += __shfl_xor_sync(0xFFFFFFFFu, sum, 2);
            sum += __shfl_xor_sync(0xFFFFFFFFu, sum, 4);
            l[r] = l[r] * corr[r] + sum;
        }
        #pragma unroll
        for (int p = 0; p < 4; p++) {
            ull c2 = pack2(corr[2*p], corr[2*p+1]);
            #pragma unroll
            for (int d = 0; d < 8; d++) O2[p][d] = fmul2(O2[p][d], c2);
        }

        __syncthreads();
        #pragma unroll
        for (int kk = 0; kk < 8; kk++) {
            int key = tk * 8 + kk;
            *(float4*)&KP[key * FP + tq * 8] =
                make_float4(s[0][kk], s[1][kk], s[2][kk], s[3][kk]);
            *(float4*)&KP[key * FP + tq * 8 + 4] =
                make_float4(s[4][kk], s[5][kk], s[6][kk], s[7][kk]);
        }
        __syncthreads();

        // ---- PV-GEMM ----
        #pragma unroll 4
        for (int key = 0; key < 64; key++) {
            ulonglong2 aa = *(const ulonglong2*)&KP[key * FP + tq * 8];
            ulonglong2 ab = *(const ulonglong2*)&KP[key * FP + tq * 8 + 4];
            ull a2[4] = {aa.x, aa.y, ab.x, ab.y};
            float4 v0 = *(const float4*)&Vs[key * FP + tk * 8];
            float4 v1 = *(const float4*)&Vs[key * FP + tk * 8 + 4];
            float bv[8] = {v0.x, v0.y, v0.z, v0.w, v1.x, v1.y, v1.z, v1.w};
            #pragma unroll
            for (int d = 0; d < 8; d++) {
                ull bb = pack2(bv[d], bv[d]);
                #pragma unroll
                for (int p = 0; p < 4; p++)
                    O2[p][d] = ffma2(a2[p], bb, O2[p][d]);
            }
        }
    }

    #pragma unroll
    for (int p = 0; p < 4; p++) {
        ull iv2 = pack2(1.f / l[2*p], 1.f / l[2*p+1]);
        #pragma unroll
        for (int d = 0; d < 8; d++) O2[p][d] = fmul2(O2[p][d], iv2);
    }
    #pragma unroll
    for (int d = 0; d < 8; d++) {
        int ch = TDF + hd * 64 + tk * 8 + d;
        float o[8];
        #pragma unroll
        for (int p = 0; p < 4; p++) {
            float2 u = unpack2(O2[p][d]);
            o[2*p] = u.x; o[2*p+1] = u.y;
        }
        float* dst = out + ((size_t)(b * DIMF + ch)) * NTOK + q0 + tq * 8;
        *(float4*)dst       = make_float4(o[0], o[1], o[2], o[3]);
        *(float4*)(dst + 4) = make_float4(o[4], o[5], o[6], o[7]);
    }
}

// ---------------------------------------------------------------------------
extern "C" void kernel_launch(void* const* d_in, const int* in_sizes, int n_in,
                              void* d_out, int out_size)
{
    const float* xa  = (const float*)d_in[0];
    const float* p1  = (const float*)d_in[1];
    const float* p2  = (const float*)d_in[2];
    const float* wu  = (const float*)d_in[3];
    const float* wd  = (const float*)d_in[4];
    const float* lw0 = (const float*)d_in[5];
    const float* lb0 = (const float*)d_in[6];
    const float* lw1 = (const float*)d_in[7];
    const float* lb1 = (const float*)d_in[8];
    float* out = (float*)d_out;

    const int cswin_smem = (2 * 392 * 48 + 9 * 48 + 48) * 4;   // 152448 B
    const int flash_smem = 3 * 64 * FP * 4;                    // 52224 B
    cudaFuncSetAttribute(cswin_kernel,
                         cudaFuncAttributeMaxDynamicSharedMemorySize, cswin_smem);
    cudaFuncSetAttribute(flash_dn_kernel,
                         cudaFuncAttributeMaxDynamicSharedMemorySize, flash_smem);

    gemm1_kernel<<<dim3(MTOT / 256, DIMF / 64), 256>>>(xa, p1, p2);
    gemm2_kernel<<<dim3(MTOT / 256, 1152 / 64), 256>>>(wu, wd);
    ktrans_kernel<<<12 * 16 * NTOK / 256, 256>>>();
    cswin_kernel<<<dim3(32, 2, 2), 256, cswin_smem>>>(lw0, lb0, lw1, lb1, out);
    flash_dn_kernel<<<dim3(NTOK / 64, 3, NB), 64, flash_smem>>>(out);
}